// round 2
// baseline (speedup 1.0000x reference)
#include <cuda_runtime.h>
#include <cstdint>

#define BB 4
#define NN 4096
#define DD 1024
#define EE 64
#define CAP 128
#define NT (BB*NN)                       // 16384 tokens
#define BNEC ((size_t)NT*EE*CAP)         // 134217728 elements per big tensor
#define THRESH 0.2f

// ---------------- scratch (no allocations allowed) ----------------
__device__ int   g_idx1[NT], g_idx2[NT];
__device__ float g_g1[NT],  g_g2[NT];
__device__ int   g_pos1[NT], g_pos2[NT];
__device__ float g_dens[BB*EE];
__device__ int   g_cnt1[BB*EE];
__device__ float g_lse;

// ---------------- init: zero accumulators (graph-replay safe) ----------------
__global__ void init_kernel() {
    int tid = threadIdx.x;
    if (tid < BB*EE) { g_dens[tid] = 0.f; g_cnt1[tid] = 0; }
    if (tid == 0) g_lse = 0.f;
}

// ---------------- fused GEMM + softmax + top2 + aux stats ----------------
// One block = 64 tokens (all within one batch since 4096 % 64 == 0).
// 256 threads: thread (tg,eg) accumulates 4 tokens x 4 experts.
__global__ __launch_bounds__(256) void gating_kernel(const float* __restrict__ x,
                                                     const float* __restrict__ w) {
    __shared__ float xs[16][64];      // [k][token]
    __shared__ float ws[16][64];      // [k][expert]
    __shared__ float logits[64][65];  // padded
    __shared__ float probs[64][65];   // un-normalized exp(l - m), padded
    __shared__ float sm_invS[64];
    __shared__ float sdens[64];
    __shared__ int   scnt[64];
    __shared__ float slse;

    const int tid = threadIdx.x;
    const int bt  = blockIdx.x;
    const int t0  = bt * 64;
    const int eg = tid & 15, tg = tid >> 4;

    float acc[4][4];
    #pragma unroll
    for (int i = 0; i < 4; i++)
        #pragma unroll
        for (int j = 0; j < 4; j++) acc[i][j] = 0.f;

    const int xtok = tid >> 2, xkq = tid & 3;   // x-tile loader mapping
    const int wkk  = tid >> 4, weq = tid & 15;  // w-tile loader mapping

    // float4 base pointers for this thread's loads
    const float4* xg = (const float4*)(x) + (size_t)(t0 + xtok) * (DD/4) + xkq;
    const float4* wg = (const float4*)(w) + (size_t)wkk * (EE/4) + weq;

    float4 xv = xg[0];
    float4 wv = wg[0];

    for (int kc = 0; kc < DD/16; kc++) {
        __syncthreads();
        xs[xkq*4+0][xtok] = xv.x;
        xs[xkq*4+1][xtok] = xv.y;
        xs[xkq*4+2][xtok] = xv.z;
        xs[xkq*4+3][xtok] = xv.w;
        *(float4*)&ws[wkk][weq*4] = wv;
        __syncthreads();
        if (kc < DD/16 - 1) {
            xv = xg[(size_t)(kc+1)*4];            // +16 floats along D
            wv = wg[(size_t)(kc+1)*16*(EE/4)];    // +16 rows of w
        }
        #pragma unroll
        for (int kk = 0; kk < 16; kk++) {
            float4 a  = *(const float4*)&xs[kk][tg*4];
            float4 bv = *(const float4*)&ws[kk][eg*4];
            acc[0][0] += a.x*bv.x; acc[0][1] += a.x*bv.y; acc[0][2] += a.x*bv.z; acc[0][3] += a.x*bv.w;
            acc[1][0] += a.y*bv.x; acc[1][1] += a.y*bv.y; acc[1][2] += a.y*bv.z; acc[1][3] += a.y*bv.w;
            acc[2][0] += a.z*bv.x; acc[2][1] += a.z*bv.y; acc[2][2] += a.z*bv.z; acc[2][3] += a.z*bv.w;
            acc[3][0] += a.w*bv.x; acc[3][1] += a.w*bv.y; acc[3][2] += a.w*bv.z; acc[3][3] += a.w*bv.w;
        }
    }

    #pragma unroll
    for (int i = 0; i < 4; i++)
        #pragma unroll
        for (int j = 0; j < 4; j++)
            logits[tg*4+i][eg*4+j] = acc[i][j];

    if (tid < 64) { sdens[tid] = 0.f; scnt[tid] = 0; }
    if (tid == 0) slse = 0.f;
    __syncthreads();

    if (tid < 64) {
        const int t = tid;
        // top-2 over logits (softmax is monotonic; strict > keeps first index on ties,
        // matching jnp.argmax for both top-1 and masked top-2)
        float best1 = -3.4e38f, best2 = -3.4e38f;
        int i1 = 0, i2 = 0;
        #pragma unroll 4
        for (int e = 0; e < EE; e++) {
            float l = logits[t][e];
            if (l > best1) { best2 = best1; i2 = i1; best1 = l; i1 = e; }
            else if (l > best2) { best2 = l; i2 = e; }
        }
        float S = 0.f;
        #pragma unroll 4
        for (int e = 0; e < EE; e++) {
            float p = __expf(logits[t][e] - best1);
            probs[t][e] = p;
            S += p;
        }
        float invS = 1.0f / S;
        sm_invS[t] = invS;
        float g1 = invS;                         // exp(best1-best1)*invS
        float g2 = __expf(best2 - best1) * invS;
        float denom = g1 + g2 + 1e-9f;
        float g1n = g1 / denom, g2n = g2 / denom;
        g_idx1[t0 + t] = i1;
        g_idx2[t0 + t] = i2;
        g_g1[t0 + t] = g1n;
        g_g2[t0 + t] = g2n;
        atomicAdd(&scnt[i1], 1);
        atomicAdd(&slse, best1 + __logf(S));
    }
    __syncthreads();

    if (tid < 64) {
        float s = 0.f;
        #pragma unroll 4
        for (int t = 0; t < 64; t++) s += probs[t][tid] * sm_invS[t];
        int b = t0 >> 12;   // t0 / 4096
        atomicAdd(&g_dens[b*EE + tid], s);
        atomicAdd(&g_cnt1[b*EE + tid], scnt[tid]);
    }
    if (tid == 0) atomicAdd(&g_lse, slse);
}

// ---------------- per-batch capacity scan ----------------
// One block per batch, 1024 threads = 32 warps, 4 chunks of 1024 tokens.
__global__ __launch_bounds__(1024) void scan_kernel() {
    __shared__ int hist[32][64];
    __shared__ int base[64];

    const int b    = blockIdx.x;
    const int tid  = threadIdx.x;
    const int wid  = tid >> 5;
    const int lane = tid & 31;
    const unsigned lt = (1u << lane) - 1u;

    if (tid < 64) base[tid] = 0;
    __syncthreads();

    // ---- phase 1: top-1 positions ----
    for (int c = 0; c < 4; c++) {
        const int t = b * NN + c * 1024 + tid;
        const int e = g_idx1[t];

        ((int*)hist)[tid] = 0;
        ((int*)hist)[tid + 1024] = 0;
        __syncthreads();

        unsigned mm = __match_any_sync(0xffffffffu, e);
        int rank = __popc(mm & lt);
        if (rank == 0) hist[wid][e] = __popc(mm);
        __syncthreads();

        if (tid < 64) {
            int run = base[tid];
            #pragma unroll 8
            for (int wq = 0; wq < 32; wq++) {
                int h = hist[wq][tid];
                hist[wq][tid] = run;
                run += h;
            }
            base[tid] = run;
        }
        __syncthreads();

        int pos = hist[wid][e] + rank;
        g_pos1[t] = (pos < CAP) ? pos : -1;
        __syncthreads();
    }

    // base -> capped mask_1_count (offset for phase 2)
    if (tid < 64) base[tid] = min(base[tid], CAP);
    __syncthreads();

    // ---- phase 2: top-2 positions (only tokens with normalized gate2 > THRESH) ----
    for (int c = 0; c < 4; c++) {
        const int t = b * NN + c * 1024 + tid;
        const bool valid = g_g2[t] > THRESH;
        const int e = valid ? g_idx2[t] : -1;

        ((int*)hist)[tid] = 0;
        ((int*)hist)[tid + 1024] = 0;
        __syncthreads();

        unsigned mm = __match_any_sync(0xffffffffu, e);
        int rank = __popc(mm & lt);
        if (valid && rank == 0) hist[wid][e] = __popc(mm);
        __syncthreads();

        if (tid < 64) {
            int run = base[tid];
            #pragma unroll 8
            for (int wq = 0; wq < 32; wq++) {
                int h = hist[wq][tid];
                hist[wq][tid] = run;
                run += h;
            }
            base[tid] = run;
        }
        __syncthreads();

        if (valid) {
            int pos = hist[wid][e] + rank;
            g_pos2[t] = (pos < CAP) ? pos : -1;
        } else {
            g_pos2[t] = -1;
        }
        __syncthreads();
    }
}

// ---------------- fused output writer (the bandwidth bottleneck) ----------------
// One block per token; writes its [64 experts x 128 cap] row of both dispatch
// and combine (32 KiB each) via STG.128, inserting the <=2 nonzeros inline.
__global__ __launch_bounds__(128) void write_kernel(float* __restrict__ out) {
    const int t   = blockIdx.x;
    const int tid = threadIdx.x;

    const int p1 = g_pos1[t], p2 = g_pos2[t];
    const int e1 = g_idx1[t], e2 = g_idx2[t];
    const float g1 = g_g1[t], g2 = g_g2[t];
    const int t1 = (p1 >= 0) ? e1 * CAP + p1 : -1;
    const int t2 = (p2 >= 0) ? e2 * CAP + p2 : -1;

    float4* __restrict__ disp = (float4*)(out + (size_t)t * (EE*CAP));
    float4* __restrict__ comb = (float4*)(out + BNEC + (size_t)t * (EE*CAP));

    #pragma unroll
    for (int i = 0; i < 16; i++) {
        const int q = tid + i * 128;        // float4 index within the 8192-elem row
        const int base4 = q * 4;
        float4 c, d;

        float cx = 0.f, dx = 0.f;
        if (base4 + 0 == t1) { cx = g1; dx = 1.f; }
        if (base4 + 0 == t2) { cx = g2; dx = 1.f; }
        float cy = 0.f, dy = 0.f;
        if (base4 + 1 == t1) { cy = g1; dy = 1.f; }
        if (base4 + 1 == t2) { cy = g2; dy = 1.f; }
        float cz = 0.f, dz = 0.f;
        if (base4 + 2 == t1) { cz = g1; dz = 1.f; }
        if (base4 + 2 == t2) { cz = g2; dz = 1.f; }
        float cw = 0.f, dw = 0.f;
        if (base4 + 3 == t1) { cw = g1; dw = 1.f; }
        if (base4 + 3 == t2) { cw = g2; dw = 1.f; }

        c.x = cx; c.y = cy; c.z = cz; c.w = cw;
        d.x = dx; d.y = dy; d.z = dz; d.w = dw;
        comb[q] = c;
        disp[q] = d;
    }
}

// ---------------- scalar losses ----------------
__global__ void finalize_kernel(float* __restrict__ out) {
    __shared__ float red[256];
    const int tid = threadIdx.x;
    red[tid] = g_dens[tid] * (float)g_cnt1[tid];
    __syncthreads();
    for (int s = 128; s > 0; s >>= 1) {
        if (tid < s) red[tid] += red[tid + s];
        __syncthreads();
    }
    if (tid == 0) {
        // loss = E/(B*N^2) * sum_{b,e}(dens * cnt1)
        out[2*BNEC]     = red[0] * ((float)EE / ((float)BB * (float)NN * (float)NN));
        out[2*BNEC + 1] = g_lse * (1.0f / (float)BB);
    }
}

// ---------------- launch ----------------
extern "C" void kernel_launch(void* const* d_in, const int* in_sizes, int n_in,
                              void* d_out, int out_size) {
    const float* x = (const float*)d_in[0];   // [4,4096,1024] f32
    const float* w = (const float*)d_in[1];   // [1024,64] f32
    float* out = (float*)d_out;               // dispatch | combine | loss | z_loss

    init_kernel<<<1, 256>>>();
    gating_kernel<<<NT/64, 256>>>(x, w);
    scan_kernel<<<BB, 1024>>>();
    write_kernel<<<NT, 128>>>(out);
    finalize_kernel<<<1, 256>>>(out);
}

// round 3
// speedup vs baseline: 1.1150x; 1.1150x over previous
#include <cuda_runtime.h>
#include <cstdint>

#define BB 4
#define NN 4096
#define DD 1024
#define EE 64
#define CAP 128
#define NT (BB*NN)                       // 16384 tokens
#define BNEC ((size_t)NT*EE*CAP)         // 134217728 elements per big tensor
#define THRESH 0.2f

// ---------------- scratch (no allocations allowed) ----------------
__device__ int   g_idx1[NT], g_idx2[NT];
__device__ float g_g1[NT],  g_g2[NT];
__device__ int   g_pos1[NT], g_pos2[NT];
__device__ float g_dens[BB*EE];
__device__ int   g_cnt1[BB*EE];
__device__ float g_lse;

// ---------------- init: zero accumulators (graph-replay safe) ----------------
__global__ void init_kernel() {
    int tid = threadIdx.x;
    if (tid < BB*EE) { g_dens[tid] = 0.f; g_cnt1[tid] = 0; }
    if (tid == 0) g_lse = 0.f;
}

// ---------------- fused GEMM + softmax + top2 + aux stats + ZERO-FILL ----------------
// One block = 64 tokens. 256 threads: thread (tg,eg) accumulates 4 tokens x 4 experts.
// The block also streams zeros over its 64 tokens' output rows (4 MiB across both
// tensors), interleaved into the k-loop: stores ride the LSU/DRAM pipes while the
// GEMM occupies the FMA pipe, so the GEMM is hidden under the mandatory store stream.
__global__ __launch_bounds__(256) void fused_kernel(const float* __restrict__ x,
                                                    const float* __restrict__ w,
                                                    float* __restrict__ out) {
    __shared__ float xs[16][64];      // [k][token]
    __shared__ float ws[16][64];      // [k][expert]
    __shared__ float logits[64][65];  // padded
    __shared__ float probs[64][65];   // un-normalized exp(l - m), padded
    __shared__ float sm_invS[64];
    __shared__ int   scnt[64];
    __shared__ float slse;

    const int tid = threadIdx.x;
    const int bt  = blockIdx.x;
    const int t0  = bt * 64;
    const int eg = tid & 15, tg = tid >> 4;

    float acc[4][4];
    #pragma unroll
    for (int i = 0; i < 4; i++)
        #pragma unroll
        for (int j = 0; j < 4; j++) acc[i][j] = 0.f;

    const int xtok = tid >> 2, xkq = tid & 3;   // x-tile loader mapping
    const int wkk  = tid >> 4, weq = tid & 15;  // w-tile loader mapping

    const float4* xg = (const float4*)(x) + (size_t)(t0 + xtok) * (DD/4) + xkq;
    const float4* wg = (const float4*)(w) + (size_t)wkk * (EE/4) + weq;

    float4 xv = xg[0];
    float4 wv = wg[0];

    // zero-fill region for this block: float4 [t0*2048, t0*2048 + 131072) in each tensor
    float4* __restrict__ dzero = (float4*)(out) + (size_t)t0 * 2048;
    float4* __restrict__ czero = (float4*)(out + BNEC) + (size_t)t0 * 2048;
    const float4 z4 = make_float4(0.f, 0.f, 0.f, 0.f);

    for (int kc = 0; kc < DD/16; kc++) {
        __syncthreads();
        xs[xkq*4+0][xtok] = xv.x;
        xs[xkq*4+1][xtok] = xv.y;
        xs[xkq*4+2][xtok] = xv.z;
        xs[xkq*4+3][xtok] = xv.w;
        *(float4*)&ws[wkk][weq*4] = wv;
        __syncthreads();
        if (kc < DD/16 - 1) {
            xv = xg[(size_t)(kc+1)*4];            // +16 floats along D
            wv = wg[(size_t)(kc+1)*16*(EE/4)];    // +16 rows of w
        }

        // ---- zero-fill burst: 2048 float4 per tensor per iteration (64 KiB total) ----
        {
            const size_t zo = (size_t)kc * 2048 + tid;
            #pragma unroll
            for (int j = 0; j < 8; j++) {
                __stcs(&dzero[zo + j*256], z4);
                __stcs(&czero[zo + j*256], z4);
            }
        }

        #pragma unroll
        for (int kk = 0; kk < 16; kk++) {
            float4 a  = *(const float4*)&xs[kk][tg*4];
            float4 bv = *(const float4*)&ws[kk][eg*4];
            acc[0][0] += a.x*bv.x; acc[0][1] += a.x*bv.y; acc[0][2] += a.x*bv.z; acc[0][3] += a.x*bv.w;
            acc[1][0] += a.y*bv.x; acc[1][1] += a.y*bv.y; acc[1][2] += a.y*bv.z; acc[1][3] += a.y*bv.w;
            acc[2][0] += a.z*bv.x; acc[2][1] += a.z*bv.y; acc[2][2] += a.z*bv.z; acc[2][3] += a.z*bv.w;
            acc[3][0] += a.w*bv.x; acc[3][1] += a.w*bv.y; acc[3][2] += a.w*bv.z; acc[3][3] += a.w*bv.w;
        }
    }

    #pragma unroll
    for (int i = 0; i < 4; i++)
        #pragma unroll
        for (int j = 0; j < 4; j++)
            logits[tg*4+i][eg*4+j] = acc[i][j];

    if (tid < 64) scnt[tid] = 0;
    if (tid == 0) slse = 0.f;
    __syncthreads();

    if (tid < 64) {
        const int t = tid;
        // top-2 over logits (softmax monotonic; strict > keeps first index on ties)
        float best1 = -3.4e38f, best2 = -3.4e38f;
        int i1 = 0, i2 = 0;
        #pragma unroll 4
        for (int e = 0; e < EE; e++) {
            float l = logits[t][e];
            if (l > best1) { best2 = best1; i2 = i1; best1 = l; i1 = e; }
            else if (l > best2) { best2 = l; i2 = e; }
        }
        float S = 0.f;
        #pragma unroll 4
        for (int e = 0; e < EE; e++) {
            float p = __expf(logits[t][e] - best1);
            probs[t][e] = p;
            S += p;
        }
        float invS = 1.0f / S;
        sm_invS[t] = invS;
        float g1 = invS;                         // exp(best1-best1)*invS
        float g2 = __expf(best2 - best1) * invS;
        float denom = g1 + g2 + 1e-9f;
        g_idx1[t0 + t] = i1;
        g_idx2[t0 + t] = i2;
        g_g1[t0 + t] = g1 / denom;
        g_g2[t0 + t] = g2 / denom;
        atomicAdd(&scnt[i1], 1);
        atomicAdd(&slse, best1 + __logf(S));
    }
    __syncthreads();

    if (tid < 64) {
        float s = 0.f;
        #pragma unroll 4
        for (int t = 0; t < 64; t++) s += probs[t][tid] * sm_invS[t];
        int b = t0 >> 12;   // t0 / 4096
        atomicAdd(&g_dens[b*EE + tid], s);
        atomicAdd(&g_cnt1[b*EE + tid], scnt[tid]);
    }
    if (tid == 0) atomicAdd(&g_lse, slse);
}

// ---------------- per-batch capacity scan ----------------
// One block per batch, 1024 threads = 32 warps, 4 chunks of 1024 tokens.
__global__ __launch_bounds__(1024) void scan_kernel() {
    __shared__ int hist[32][64];
    __shared__ int base[64];

    const int b    = blockIdx.x;
    const int tid  = threadIdx.x;
    const int wid  = tid >> 5;
    const int lane = tid & 31;
    const unsigned lt = (1u << lane) - 1u;

    if (tid < 64) base[tid] = 0;
    __syncthreads();

    // ---- phase 1: top-1 positions ----
    for (int c = 0; c < 4; c++) {
        const int t = b * NN + c * 1024 + tid;
        const int e = g_idx1[t];

        ((int*)hist)[tid] = 0;
        ((int*)hist)[tid + 1024] = 0;
        __syncthreads();

        unsigned mm = __match_any_sync(0xffffffffu, e);
        int rank = __popc(mm & lt);
        if (rank == 0) hist[wid][e] = __popc(mm);
        __syncthreads();

        if (tid < 64) {
            int run = base[tid];
            #pragma unroll 8
            for (int wq = 0; wq < 32; wq++) {
                int h = hist[wq][tid];
                hist[wq][tid] = run;
                run += h;
            }
            base[tid] = run;
        }
        __syncthreads();

        int pos = hist[wid][e] + rank;
        g_pos1[t] = (pos < CAP) ? pos : -1;
        __syncthreads();
    }

    // base -> capped mask_1_count (offset for phase 2)
    if (tid < 64) base[tid] = min(base[tid], CAP);
    __syncthreads();

    // ---- phase 2: top-2 positions (only tokens with normalized gate2 > THRESH) ----
    for (int c = 0; c < 4; c++) {
        const int t = b * NN + c * 1024 + tid;
        const bool valid = g_g2[t] > THRESH;
        const int e = valid ? g_idx2[t] : -1;

        ((int*)hist)[tid] = 0;
        ((int*)hist)[tid + 1024] = 0;
        __syncthreads();

        unsigned mm = __match_any_sync(0xffffffffu, e);
        int rank = __popc(mm & lt);
        if (valid && rank == 0) hist[wid][e] = __popc(mm);
        __syncthreads();

        if (tid < 64) {
            int run = base[tid];
            #pragma unroll 8
            for (int wq = 0; wq < 32; wq++) {
                int h = hist[wq][tid];
                hist[wq][tid] = run;
                run += h;
            }
            base[tid] = run;
        }
        __syncthreads();

        if (valid) {
            int pos = hist[wid][e] + rank;
            g_pos2[t] = (pos < CAP) ? pos : -1;
        } else {
            g_pos2[t] = -1;
        }
        __syncthreads();
    }
}

// ---------------- scatter: write only the nonzeros (replaces the 149us writer) ----------------
__global__ __launch_bounds__(256) void scatter_kernel(float* __restrict__ out) {
    const int t = blockIdx.x * 256 + threadIdx.x;
    if (t >= NT) return;

    const int p1 = g_pos1[t], p2 = g_pos2[t];
    const size_t row = (size_t)t * (EE*CAP);

    if (p1 >= 0) {
        const size_t o = row + (size_t)g_idx1[t] * CAP + p1;
        out[o]        = 1.f;       // dispatch
        out[BNEC + o] = g_g1[t];   // combine
    }
    if (p2 >= 0) {
        const size_t o = row + (size_t)g_idx2[t] * CAP + p2;
        out[o]        = 1.f;
        out[BNEC + o] = g_g2[t];
    }
}

// ---------------- scalar losses ----------------
__global__ void finalize_kernel(float* __restrict__ out) {
    __shared__ float red[256];
    const int tid = threadIdx.x;
    red[tid] = g_dens[tid] * (float)g_cnt1[tid];
    __syncthreads();
    for (int s = 128; s > 0; s >>= 1) {
        if (tid < s) red[tid] += red[tid + s];
        __syncthreads();
    }
    if (tid == 0) {
        // loss = E/(B*N^2) * sum_{b,e}(dens * cnt1)
        out[2*BNEC]     = red[0] * ((float)EE / ((float)BB * (float)NN * (float)NN));
        out[2*BNEC + 1] = g_lse * (1.0f / (float)BB);
    }
}

// ---------------- launch ----------------
extern "C" void kernel_launch(void* const* d_in, const int* in_sizes, int n_in,
                              void* d_out, int out_size) {
    const float* x = (const float*)d_in[0];   // [4,4096,1024] f32
    const float* w = (const float*)d_in[1];   // [1024,64] f32
    float* out = (float*)d_out;               // dispatch | combine | loss | z_loss

    init_kernel<<<1, 256>>>();
    fused_kernel<<<NT/64, 256>>>(x, w, out);
    scan_kernel<<<BB, 1024>>>();
    scatter_kernel<<<NT/256, 256>>>(out);
    finalize_kernel<<<1, 256>>>(out);
}